// round 15
// baseline (speedup 1.0000x reference)
#include <cuda_runtime.h>
#include <cstdint>

#define NB    32
#define CIN   256
#define HH    56
#define WW    56
#define KOUT  256
#define NPIX  (HH*WW)        // 3136
#define KDIM  (CIN*9)        // 2304
#define NCHUNK 72            // 8 c-groups x 9 taps (32 k each)
#define NTILES 1792          // 28 r-tiles(2 rows) x 2 k-groups x 32 images

// smem: B halo ping-pong only: 2 x (232 rows x 128B)
#define B_ROWS  232          // 4 input rows x 58 cols
#define B_STAGE (B_ROWS*128) // 29696
#define B_SLOTS (B_ROWS*8)   // 1856 vec16 slots
#define SM_DYN (2*B_STAGE + 256)   // ~59.6KB/CTA -> 2 CTAs/SM

// ---------------- device scratch -------------------------------------------
// A in fragment order: [k0g][chunk][wm][mi][ks][lane] x 4 tf32 (16B per lane)
#define WA_FLOATS (2*NCHUNK*4*2*4*32*4)   // 589824 floats = 2.36MB
__device__ __align__(16) float g_wa[WA_FLOATS];
__device__ __align__(16) float g_xt[(size_t)NB * NPIX * CIN];   // NHWC tf32
__device__ unsigned int g_tile_ctr;

// ---------------- PTX helpers ----------------------------------------------
__device__ __forceinline__ uint32_t smem_u32(const void* p) {
    uint32_t a;
    asm("{ .reg .u64 t; cvta.to.shared.u64 t, %1; cvt.u32.u64 %0, t; }"
        : "=r"(a) : "l"(p));
    return a;
}
__device__ __forceinline__ float to_tf32(float v) {
    uint32_t r;
    asm("cvt.rna.tf32.f32 %0, %1;" : "=r"(r) : "f"(v));
    return __uint_as_float(r);
}

#define CP16(dst, src, sz) \
    asm volatile("cp.async.cg.shared.global [%0], [%1], 16, %2;" \
                 :: "r"(dst), "l"(src), "r"(sz) : "memory")
#define CP_COMMIT() asm volatile("cp.async.commit_group;" ::: "memory")
#define CP_WAIT0()  asm volatile("cp.async.wait_group 0;" ::: "memory")

#define LDSM4(r, a) \
    asm volatile("ldmatrix.sync.aligned.m8n8.x4.shared.b16 {%0,%1,%2,%3}, [%4];" \
                 : "=r"((r)[0]),"=r"((r)[1]),"=r"((r)[2]),"=r"((r)[3]) : "r"(a))
#define LDSM2(r, a) \
    asm volatile("ldmatrix.sync.aligned.m8n8.x2.shared.b16 {%0,%1}, [%2];" \
                 : "=r"((r)[0]),"=r"((r)[1]) : "r"(a))

#define MMAT(d, a, b) \
    asm volatile("mma.sync.aligned.m16n8k8.row.col.f32.tf32.tf32.f32 " \
                 "{%0,%1,%2,%3}, {%4,%5,%6,%7}, {%8,%9}, {%0,%1,%2,%3};" \
                 : "+f"((d)[0]),"+f"((d)[1]),"+f"((d)[2]),"+f"((d)[3]) \
                 : "r"((a).x),"r"((a).y),"r"((a).z),"r"((a).w), \
                   "r"((b)[0]),"r"((b)[1]))

// ---------------- fused prepass (unchanged from R14) -------------------------
__global__ void prepass_all(const float* __restrict__ x,
                            const float* __restrict__ w) {
    __shared__ float t[32][33];
    const int tx = threadIdx.x, ty = threadIdx.y;   // 32 x 8

    if (blockIdx.z < NB) {
        const int n  = blockIdx.z;
        const int p0 = blockIdx.x * 32;
        const int c0 = blockIdx.y * 32;

        const float* xb = x + ((size_t)n * CIN + c0) * NPIX + p0;
        #pragma unroll
        for (int yy = ty; yy < 32; yy += 8)
            t[yy][tx] = xb[(size_t)yy * NPIX + tx];
        __syncthreads();

        size_t ob = ((size_t)n * NPIX + p0) * CIN + c0;
        #pragma unroll
        for (int yy = ty; yy < 32; yy += 8)
            g_xt[ob + (size_t)yy * CIN + tx] = to_tf32(t[tx][yy]);
    } else {
        const int b = blockIdx.y * gridDim.x + blockIdx.x;   // 0..783
        const int tl = ty * 32 + tx;
        const int idx = b * 256 + tl;
        if (idx == 0) g_tile_ctr = 0u;
        if (idx < WA_FLOATS / 4) {
            const int L  = idx & 31;
            int r = idx >> 5;
            const int ks = r & 3;  r >>= 2;
            const int mi = r & 1;  r >>= 1;
            const int wm = r & 3;  r >>= 2;
            const int ch  = r % NCHUNK;
            const int k0g = r / NCHUNK;
            const int cg = ch / 9, tap = ch - (ch / 9) * 9;
            const int row0 = k0g * 128 + wm * 32 + mi * 16 + (L >> 2);
            const int kc   = cg * 32 + ks * 8 + (L & 3);
            float4 o;
            o.x = to_tf32(w[(size_t)(row0      * CIN + kc    ) * 9 + tap]);
            o.y = to_tf32(w[(size_t)((row0 + 8)* CIN + kc    ) * 9 + tap]);
            o.z = to_tf32(w[(size_t)(row0      * CIN + kc + 4) * 9 + tap]);
            o.w = to_tf32(w[(size_t)((row0 + 8)* CIN + kc + 4) * 9 + tap]);
            reinterpret_cast<float4*>(g_wa)[idx] = o;
        }
    }
}

// ---------------- main kernel: persistent, software-pipelined ---------------
__global__ __launch_bounds__(256, 2)
void conv_mma_kernel(const float* __restrict__ bias, float* __restrict__ out)
{
    extern __shared__ __align__(16) char dsm_raw[];
    __shared__ unsigned s_tile;

    const int tid = threadIdx.x;
    const int wid = tid >> 5;
    const int L   = tid & 31;
    const int wm  = wid & 3;
    const int wn  = wid >> 2;

    uint32_t raw = smem_u32(dsm_raw);
    uint32_t sm  = (raw + 127u) & ~127u;
    uint32_t bB[2] = { sm, sm + B_STAGE };

    // ---- per-lane B ldmatrix constants ----
    const int bLane  = ((L >> 4) & 1) * 8 + (L & 7);
    const int bkg    = (L >> 3) & 1;
    const int bsLane = 48 + (L & 7);
    const int bskg   = (L >> 3) & 1;

    const uint4* __restrict__ aP = reinterpret_cast<const uint4*>(g_wa);

    // ---- B halo staging (stateless) ----
    auto stageB = [&](int tn, int tr0, int cgc, int slice, uint32_t buf) {
        const int slot = slice * 256 + tid;
        if (slot < B_SLOTS) {
            const int ri = slot >> 3, v = slot & 7;
            const int inRow = ri / 58;
            const int inCol = ri - inRow * 58;
            const int r = tr0 - 1 + inRow;
            const int w = inCol - 1;
            const bool ok = ((unsigned)r < HH) & ((unsigned)w < WW);
            const int pix = ok ? (r * WW + w) : 0;
            const float* src = g_xt + ((size_t)tn * NPIX + pix) * CIN
                                    + (cgc << 5) + (v << 2);
            uint32_t bo = (uint32_t)(ri << 7) + (v << 4);
            bo ^= (bo >> 3) & 0x70;
            CP16(buf + bo, src, ok ? 16u : 0u);
        }
    };
    // B fragment loader for (rowBase Cw, ks) into bt slot
    auto ldsmB = [&](uint32_t (&bt)[7][2], uint32_t sB, int Cw, int ks) {
        const int riP = Cw + bLane;
        #pragma unroll
        for (int pi = 0; pi < 3; ++pi) {
            const int ri = riP + pi * 16;
            const int c16 = (ks * 2 + bkg) ^ (ri & 7);
            LDSM4(&bt[pi * 2][0], sB + (uint32_t)(ri << 7) + (c16 << 4));
        }
        const int riS = Cw + bsLane;
        const int c16 = (ks * 2 + bskg) ^ (riS & 7);
        LDSM2(bt[6], sB + (uint32_t)(riS << 7) + (c16 << 4));
    };

    float acc[2][7][4];
    #pragma unroll
    for (int mi = 0; mi < 2; ++mi)
        #pragma unroll
        for (int ni = 0; ni < 7; ++ni)
            #pragma unroll
            for (int q = 0; q < 4; ++q)
                acc[mi][ni][q] = 0.0f;

    // ---- acquire first tile ----
    if (tid == 0) s_tile = atomicAdd(&g_tile_ctr, 1u);
    __syncthreads();
    if ((int)s_tile >= NTILES) return;
    int n, r0, k0g;
    {
        const int t = (int)s_tile;
        n = t / 56;
        const int rem = t - n * 56;
        k0g = rem & 1;
        r0 = (rem >> 1) << 1;
    }
    #pragma unroll
    for (int t = 0; t < 8; ++t) stageB(n, r0, 0, t, bB[0]);
    CP_COMMIT();

    const uint4* aC = aP + (size_t)(((k0g * NCHUNK) * 4 + wm) * 2) * 128 + L;

    int nn = 0, nr0 = 0, nk0g = 0;
    bool vN = false;
    int lc = 0, tap = 0, cg = 0;

    uint32_t bt[2][7][2];     // B ping-pong
    uint4    aF[2][2];        // A ping-pong: [slot][mi]

    // ---- persistent main loop ----
    while (true) {
        const uint32_t sB = bB[cg & 1];
        const int kh = tap / 3 - 1;
        const int kw = tap - (tap / 3) * 3 - 1;
        const int Cw = (wn + 1 + kh) * 58 + 1 + kw;
        // next tap's row base (valid when tap<8)
        const int tapN = tap + 1;
        const int khN = tapN / 3 - 1;
        const int kwN = tapN - (tapN / 3) * 3 - 1;
        const int CwN = (wn + 1 + khN) * 58 + 1 + kwN;

        if (tap == 0) {
            CP_WAIT0();
            __syncthreads();
            if (lc == 63) {
                const unsigned tt = s_tile;
                vN = (tt < NTILES);
                if (vN) {
                    nn = tt / 56;
                    const int rem = (int)tt - nn * 56;
                    nk0g = rem & 1;
                    nr0 = (rem >> 1) << 1;
                }
            }
            // pipeline refill: B ks0, A ks0+ks1
            ldsmB(bt[0], sB, Cw, 0);
            aF[0][0] = aC[0];        aF[0][1] = aC[128];
            aF[1][0] = aC[32];       aF[1][1] = aC[128 + 32];
        }
        if (lc == 61 && tid == 0) s_tile = atomicAdd(&g_tile_ctr, 1u);

        // ---- 4 pipelined k8-steps ----
        #pragma unroll
        for (int ks = 0; ks < 4; ++ks) {
            // 1) prefetch B for step g+1 (before this step's MMAs)
            if (ks < 3)          ldsmB(bt[(ks + 1) & 1], sB, Cw, ks + 1);
            else if (tap < 8)    ldsmB(bt[0],            sB, CwN, 0);
            // 2) staging slice (once per chunk, at ks==1)
            if (ks == 1) {
                if (tap < 8) {
                    if (cg < 7)  { stageB(n,  r0,  cg + 1, tap, bB[(cg + 1) & 1]); CP_COMMIT(); }
                    else if (vN) { stageB(nn, nr0, 0,      tap, bB[0]);            CP_COMMIT(); }
                }
            }
            // 3) MMAs of step g (bt/aF loaded >=1 iter ago)
            #pragma unroll
            for (int ni = 0; ni < 7; ++ni) {
                MMAT(acc[0][ni], aF[ks & 1][0], bt[ks & 1][ni]);
                MMAT(acc[1][ni], aF[ks & 1][1], bt[ks & 1][ni]);
            }
            // 4) A prefetch for step g+2 into the just-freed slot
            if (ks < 2) {
                aF[ks & 1][0] = aC[(ks + 2) * 32];
                aF[ks & 1][1] = aC[128 + (ks + 2) * 32];
            } else if (tap < 8) {
                aF[ks & 1][0] = aC[1024 + (ks - 2) * 32];
                aF[ks & 1][1] = aC[1024 + 128 + (ks - 2) * 32];
            }
        }
        aC += 1024;   // next chunk

        if (lc == NCHUNK - 1) {
            // ---- epilogue ----
            const int gID = L >> 2;
            const int tig = L & 3;
            const int r   = r0 + wn;
            #pragma unroll
            for (int mi = 0; mi < 2; ++mi) {
                const int kbase = k0g * 128 + wm * 32 + mi * 16 + gID;
                const float b0 = bias[kbase];
                const float b1 = bias[kbase + 8];
                float* o0 = out + (((size_t)n * KOUT + kbase)     * HH + r) * WW;
                float* o1 = out + (((size_t)n * KOUT + kbase + 8) * HH + r) * WW;
                #pragma unroll
                for (int ni = 0; ni < 7; ++ni) {
                    const int c = ni * 8 + tig * 2;
                    float2 v0 = make_float2(acc[mi][ni][0] + b0, acc[mi][ni][1] + b0);
                    float2 v1 = make_float2(acc[mi][ni][2] + b1, acc[mi][ni][3] + b1);
                    *reinterpret_cast<float2*>(o0 + c) = v0;
                    *reinterpret_cast<float2*>(o1 + c) = v1;
                }
            }
            if (!vN) break;
            #pragma unroll
            for (int mi = 0; mi < 2; ++mi)
                #pragma unroll
                for (int ni = 0; ni < 7; ++ni)
                    #pragma unroll
                    for (int q = 0; q < 4; ++q)
                        acc[mi][ni][q] = 0.0f;
            n = nn; r0 = nr0; k0g = nk0g;
            aC = aP + (size_t)(((k0g * NCHUNK) * 4 + wm) * 2) * 128 + L;
            vN = false;
            lc = 0; tap = 0; cg = 0;
        } else {
            ++lc;
            if (++tap == 9) { tap = 0; ++cg; }
        }
    }
}

// ---------------- launch -----------------------------------------------------
extern "C" void kernel_launch(void* const* d_in, const int* in_sizes, int n_in,
                              void* d_out, int out_size)
{
    const float* x    = (const float*)d_in[0];
    const float* wgt  = (const float*)d_in[1];
    const float* bias = (const float*)d_in[2];
    float* out        = (float*)d_out;

    cudaFuncSetAttribute(conv_mma_kernel,
                         cudaFuncAttributeMaxDynamicSharedMemorySize, SM_DYN);

    {
        dim3 g(NPIX / 32, CIN / 32, NB + 1);
        dim3 b(32, 8);
        prepass_all<<<g, b>>>(x, wgt);
    }

    conv_mma_kernel<<<296, 256, SM_DYN>>>(bias, out);   // persistent: 2 CTAs/SM
}

// round 16
// speedup vs baseline: 1.0209x; 1.0209x over previous
#include <cuda_runtime.h>
#include <cstdint>

#define NB    32
#define CIN   256
#define HH    56
#define WW    56
#define KOUT  256
#define NPIX  (HH*WW)        // 3136
#define KDIM  (CIN*9)        // 2304
#define NCHUNK 72            // 8 c-groups x 9 taps (32 k each)
#define NTILES 1792          // 28 r-tiles(2 rows) x 2 k-groups x 32 images

// smem: B halo ping-pong only: 2 x (232 rows x 128B)
#define B_ROWS  232          // 4 input rows x 58 cols
#define B_STAGE (B_ROWS*128) // 29696
#define B_SLOTS (B_ROWS*8)   // 1856 vec16 slots
#define SM_DYN (2*B_STAGE + 256)   // ~59.6KB/CTA -> 2 CTAs/SM

// ---------------- device scratch -------------------------------------------
// A in fragment order: [k0g][chunk][wm][mi][ks][lane] x 4 tf32 (16B per lane)
#define WA_FLOATS (2*NCHUNK*4*2*4*32*4)   // 589824 floats = 2.36MB
__device__ __align__(16) float g_wa[WA_FLOATS];
__device__ __align__(16) float g_xt[(size_t)NB * NPIX * CIN];   // NHWC tf32
__device__ unsigned int g_tile_ctr;

// ---------------- PTX helpers ----------------------------------------------
__device__ __forceinline__ uint32_t smem_u32(const void* p) {
    uint32_t a;
    asm("{ .reg .u64 t; cvta.to.shared.u64 t, %1; cvt.u32.u64 %0, t; }"
        : "=r"(a) : "l"(p));
    return a;
}
__device__ __forceinline__ float to_tf32(float v) {
    uint32_t r;
    asm("cvt.rna.tf32.f32 %0, %1;" : "=r"(r) : "f"(v));
    return __uint_as_float(r);
}

#define CP16(dst, src, sz) \
    asm volatile("cp.async.cg.shared.global [%0], [%1], 16, %2;" \
                 :: "r"(dst), "l"(src), "r"(sz) : "memory")
#define CP_COMMIT() asm volatile("cp.async.commit_group;" ::: "memory")
#define CP_WAIT0()  asm volatile("cp.async.wait_group 0;" ::: "memory")

#define LDSM4(r, a) \
    asm volatile("ldmatrix.sync.aligned.m8n8.x4.shared.b16 {%0,%1,%2,%3}, [%4];" \
                 : "=r"((r)[0]),"=r"((r)[1]),"=r"((r)[2]),"=r"((r)[3]) : "r"(a))
#define LDSM2(r, a) \
    asm volatile("ldmatrix.sync.aligned.m8n8.x2.shared.b16 {%0,%1}, [%2];" \
                 : "=r"((r)[0]),"=r"((r)[1]) : "r"(a))

#define MMAT(d, a, b) \
    asm volatile("mma.sync.aligned.m16n8k8.row.col.f32.tf32.tf32.f32 " \
                 "{%0,%1,%2,%3}, {%4,%5,%6,%7}, {%8,%9}, {%0,%1,%2,%3};" \
                 : "+f"((d)[0]),"+f"((d)[1]),"+f"((d)[2]),"+f"((d)[3]) \
                 : "r"((a).x),"r"((a).y),"r"((a).z),"r"((a).w), \
                   "r"((b)[0]),"r"((b)[1]))

#define PF_L1(p) asm volatile("prefetch.global.L1 [%0];" :: "l"(p))

// ---------------- fused prepass (unchanged from R14) -------------------------
__global__ void prepass_all(const float* __restrict__ x,
                            const float* __restrict__ w) {
    __shared__ float t[32][33];
    const int tx = threadIdx.x, ty = threadIdx.y;   // 32 x 8

    if (blockIdx.z < NB) {
        const int n  = blockIdx.z;
        const int p0 = blockIdx.x * 32;
        const int c0 = blockIdx.y * 32;

        const float* xb = x + ((size_t)n * CIN + c0) * NPIX + p0;
        #pragma unroll
        for (int yy = ty; yy < 32; yy += 8)
            t[yy][tx] = xb[(size_t)yy * NPIX + tx];
        __syncthreads();

        size_t ob = ((size_t)n * NPIX + p0) * CIN + c0;
        #pragma unroll
        for (int yy = ty; yy < 32; yy += 8)
            g_xt[ob + (size_t)yy * CIN + tx] = to_tf32(t[tx][yy]);
    } else {
        const int b = blockIdx.y * gridDim.x + blockIdx.x;   // 0..783
        const int tl = ty * 32 + tx;
        const int idx = b * 256 + tl;
        if (idx == 0) g_tile_ctr = 0u;
        if (idx < WA_FLOATS / 4) {
            const int L  = idx & 31;
            int r = idx >> 5;
            const int ks = r & 3;  r >>= 2;
            const int mi = r & 1;  r >>= 1;
            const int wm = r & 3;  r >>= 2;
            const int ch  = r % NCHUNK;
            const int k0g = r / NCHUNK;
            const int cg = ch / 9, tap = ch - (ch / 9) * 9;
            const int row0 = k0g * 128 + wm * 32 + mi * 16 + (L >> 2);
            const int kc   = cg * 32 + ks * 8 + (L & 3);
            float4 o;
            o.x = to_tf32(w[(size_t)(row0      * CIN + kc    ) * 9 + tap]);
            o.y = to_tf32(w[(size_t)((row0 + 8)* CIN + kc    ) * 9 + tap]);
            o.z = to_tf32(w[(size_t)(row0      * CIN + kc + 4) * 9 + tap]);
            o.w = to_tf32(w[(size_t)((row0 + 8)* CIN + kc + 4) * 9 + tap]);
            reinterpret_cast<float4*>(g_wa)[idx] = o;
        }
    }
}

// ---------------- main kernel: persistent, A-LDG + L1 prefetch --------------
__global__ __launch_bounds__(256, 2)
void conv_mma_kernel(const float* __restrict__ bias, float* __restrict__ out)
{
    extern __shared__ __align__(16) char dsm_raw[];
    __shared__ unsigned s_tile;

    const int tid = threadIdx.x;
    const int wid = tid >> 5;
    const int L   = tid & 31;
    const int wm  = wid & 3;             // M quarter
    const int wn  = wid >> 2;            // output row within 2-row tile

    uint32_t raw = smem_u32(dsm_raw);
    uint32_t sm  = (raw + 127u) & ~127u;
    uint32_t bB[2] = { sm, sm + B_STAGE };

    // ---- per-lane B ldmatrix constants ----
    const int bLane  = ((L >> 4) & 1) * 8 + (L & 7);
    const int bkg    = (L >> 3) & 1;
    const int bsLane = 48 + (L & 7);
    const int bskg   = (L >> 3) & 1;

    const uint4* __restrict__ aP = reinterpret_cast<const uint4*>(g_wa);

    // ---- B halo staging (stateless) ----
    auto stageB = [&](int tn, int tr0, int cgc, int slice, uint32_t buf) {
        const int slot = slice * 256 + tid;
        if (slot < B_SLOTS) {
            const int ri = slot >> 3, v = slot & 7;
            const int inRow = ri / 58;
            const int inCol = ri - inRow * 58;
            const int r = tr0 - 1 + inRow;
            const int w = inCol - 1;
            const bool ok = ((unsigned)r < HH) & ((unsigned)w < WW);
            const int pix = ok ? (r * WW + w) : 0;
            const float* src = g_xt + ((size_t)tn * NPIX + pix) * CIN
                                    + (cgc << 5) + (v << 2);
            uint32_t bo = (uint32_t)(ri << 7) + (v << 4);
            bo ^= (bo >> 3) & 0x70;
            CP16(buf + bo, src, ok ? 16u : 0u);
        }
    };

    float acc[2][7][4];
    #pragma unroll
    for (int mi = 0; mi < 2; ++mi)
        #pragma unroll
        for (int ni = 0; ni < 7; ++ni)
            #pragma unroll
            for (int q = 0; q < 4; ++q)
                acc[mi][ni][q] = 0.0f;

    // ---- acquire first tile ----
    if (tid == 0) s_tile = atomicAdd(&g_tile_ctr, 1u);
    __syncthreads();
    if ((int)s_tile >= NTILES) return;
    int n, r0, k0g;
    {
        const int t = (int)s_tile;
        n = t / 56;
        const int rem = t - n * 56;
        k0g = rem & 1;
        r0 = (rem >> 1) << 1;
    }
    // prologue: full B halo for c-group 0
    #pragma unroll
    for (int t = 0; t < 8; ++t) stageB(n, r0, 0, t, bB[0]);
    CP_COMMIT();

    int nn = 0, nr0 = 0, nk0g = 0;
    bool vN = false;
    int lc = 0, tap = 0, cg = 0;

    // ---- persistent main loop: barrier only at c-group boundaries ----
    while (true) {
        if (tap == 0) {
            CP_WAIT0();
            __syncthreads();
            if (lc == 63) {
                const unsigned tt = s_tile;
                vN = (tt < NTILES);
                if (vN) {
                    nn = tt / 56;
                    const int rem = (int)tt - nn * 56;
                    nk0g = rem & 1;
                    nr0 = (rem >> 1) << 1;
                }
            }
        }
        if (lc == 61 && tid == 0) s_tile = atomicAdd(&g_tile_ctr, 1u);

        // stage one B halo slice for the next c-group / next tile
        if (tap < 8) {
            if (cg < 7)  { stageB(n,  r0,  cg + 1, tap, bB[(cg + 1) & 1]); CP_COMMIT(); }
            else if (vN) { stageB(nn, nr0, 0,      tap, bB[0]);            CP_COMMIT(); }
        }

        // ---- compute chunk lc: A via direct LDG, B via halo LDSM ----
        {
            const uint32_t sB = bB[cg & 1];
            const int kh = tap / 3 - 1;
            const int kw = tap - (tap / 3) * 3 - 1;
            const int Cw = (wn + 1 + kh) * 58 + 1 + kw;
            const int riP = Cw + bLane;
            const int riS = Cw + bsLane;

            // A fragments for the whole chunk: 8 coalesced LDG.128
            const uint4* aC = aP + (size_t)(((k0g * NCHUNK + lc) * 4 + wm) * 2) * 128 + L;
            uint4 aR[2][4];
            #pragma unroll
            for (int mi = 0; mi < 2; ++mi)
                #pragma unroll
                for (int ks = 0; ks < 4; ++ks)
                    aR[mi][ks] = aC[mi * 128 + ks * 32];

            // L1 prefetch of NEXT chunk's A fragments (one chunk of lead time)
            if (lc < NCHUNK - 1) {
                #pragma unroll
                for (int mi = 0; mi < 2; ++mi)
                    #pragma unroll
                    for (int ks = 0; ks < 4; ++ks)
                        PF_L1(aC + 1024 + mi * 128 + ks * 32);
            }

            #pragma unroll
            for (int ks = 0; ks < 4; ++ks) {
                uint32_t bt[7][2];
                #pragma unroll
                for (int pi = 0; pi < 3; ++pi) {
                    const int ri = riP + pi * 16;
                    const int c16 = (ks * 2 + bkg) ^ (ri & 7);
                    LDSM4(&bt[pi * 2][0], sB + (uint32_t)(ri << 7) + (c16 << 4));
                }
                {
                    const int c16 = (ks * 2 + bskg) ^ (riS & 7);
                    LDSM2(bt[6], sB + (uint32_t)(riS << 7) + (c16 << 4));
                }
                #pragma unroll
                for (int ni = 0; ni < 7; ++ni) {
                    MMAT(acc[0][ni], aR[0][ks], bt[ni]);
                    MMAT(acc[1][ni], aR[1][ks], bt[ni]);
                }
            }
        }

        if (lc == NCHUNK - 1) {
            // ---- epilogue ----
            const int gID = L >> 2;
            const int tig = L & 3;
            const int r   = r0 + wn;
            #pragma unroll
            for (int mi = 0; mi < 2; ++mi) {
                const int kbase = k0g * 128 + wm * 32 + mi * 16 + gID;
                const float b0 = bias[kbase];
                const float b1 = bias[kbase + 8];
                float* o0 = out + (((size_t)n * KOUT + kbase)     * HH + r) * WW;
                float* o1 = out + (((size_t)n * KOUT + kbase + 8) * HH + r) * WW;
                #pragma unroll
                for (int ni = 0; ni < 7; ++ni) {
                    const int c = ni * 8 + tig * 2;
                    float2 v0 = make_float2(acc[mi][ni][0] + b0, acc[mi][ni][1] + b0);
                    float2 v1 = make_float2(acc[mi][ni][2] + b1, acc[mi][ni][3] + b1);
                    *reinterpret_cast<float2*>(o0 + c) = v0;
                    *reinterpret_cast<float2*>(o1 + c) = v1;
                }
            }
            if (!vN) break;
            #pragma unroll
            for (int mi = 0; mi < 2; ++mi)
                #pragma unroll
                for (int ni = 0; ni < 7; ++ni)
                    #pragma unroll
                    for (int q = 0; q < 4; ++q)
                        acc[mi][ni][q] = 0.0f;
            n = nn; r0 = nr0; k0g = nk0g;
            vN = false;
            lc = 0; tap = 0; cg = 0;
        } else {
            ++lc;
            if (++tap == 9) { tap = 0; ++cg; }
        }
    }
}

// ---------------- launch -----------------------------------------------------
extern "C" void kernel_launch(void* const* d_in, const int* in_sizes, int n_in,
                              void* d_out, int out_size)
{
    const float* x    = (const float*)d_in[0];
    const float* wgt  = (const float*)d_in[1];
    const float* bias = (const float*)d_in[2];
    float* out        = (float*)d_out;

    cudaFuncSetAttribute(conv_mma_kernel,
                         cudaFuncAttributeMaxDynamicSharedMemorySize, SM_DYN);

    {
        dim3 g(NPIX / 32, CIN / 32, NB + 1);   // z=NB: g_wa fill + ctr reset
        dim3 b(32, 8);
        prepass_all<<<g, b>>>(x, wgt);
    }

    conv_mma_kernel<<<296, 256, SM_DYN>>>(bias, out);   // persistent: 2 CTAs/SM
}

// round 17
// speedup vs baseline: 1.0672x; 1.0454x over previous
#include <cuda_runtime.h>
#include <cstdint>

#define NB    32
#define CIN   256
#define HH    56
#define WW    56
#define KOUT  256
#define NPIX  (HH*WW)        // 3136
#define KDIM  (CIN*9)        // 2304
#define NCHUNK 72            // 8 c-groups x 9 taps (32 k each)
#define NTILES 1792          // 28 r-tiles(2 rows) x 2 k-groups x 32 images

// smem: B halo ping-pong only: 2 x (232 rows x 128B)
#define B_ROWS  232          // 4 input rows x 58 cols
#define B_STAGE (B_ROWS*128) // 29696
#define B_SLOTS (B_ROWS*8)   // 1856 vec16 slots
#define SM_DYN (2*B_STAGE + 256)   // ~59.6KB/CTA -> 2 CTAs/SM

// ---------------- device scratch -------------------------------------------
// A in fragment order: [k0g][chunk][wm][mi][ks][lane] x 4 tf32 (16B per lane)
#define WA_FLOATS (2*NCHUNK*4*2*4*32*4)   // 589824 floats = 2.36MB
__device__ __align__(16) float g_wa[WA_FLOATS];
__device__ __align__(16) float g_xt[(size_t)NB * NPIX * CIN];   // NHWC tf32
__device__ unsigned int g_tile_ctr;

// ---------------- PTX helpers ----------------------------------------------
__device__ __forceinline__ uint32_t smem_u32(const void* p) {
    uint32_t a;
    asm("{ .reg .u64 t; cvta.to.shared.u64 t, %1; cvt.u32.u64 %0, t; }"
        : "=r"(a) : "l"(p));
    return a;
}
__device__ __forceinline__ float to_tf32(float v) {
    uint32_t r;
    asm("cvt.rna.tf32.f32 %0, %1;" : "=r"(r) : "f"(v));
    return __uint_as_float(r);
}

#define CP16(dst, src, sz) \
    asm volatile("cp.async.cg.shared.global [%0], [%1], 16, %2;" \
                 :: "r"(dst), "l"(src), "r"(sz) : "memory")
#define CP_COMMIT() asm volatile("cp.async.commit_group;" ::: "memory")
#define CP_WAIT0()  asm volatile("cp.async.wait_group 0;" ::: "memory")

#define LDSM4(r, a) \
    asm volatile("ldmatrix.sync.aligned.m8n8.x4.shared.b16 {%0,%1,%2,%3}, [%4];" \
                 : "=r"((r)[0]),"=r"((r)[1]),"=r"((r)[2]),"=r"((r)[3]) : "r"(a))
#define LDSM2(r, a) \
    asm volatile("ldmatrix.sync.aligned.m8n8.x2.shared.b16 {%0,%1}, [%2];" \
                 : "=r"((r)[0]),"=r"((r)[1]) : "r"(a))

#define MMAT(d, a, b) \
    asm volatile("mma.sync.aligned.m16n8k8.row.col.f32.tf32.tf32.f32 " \
                 "{%0,%1,%2,%3}, {%4,%5,%6,%7}, {%8,%9}, {%0,%1,%2,%3};" \
                 : "+f"((d)[0]),"+f"((d)[1]),"+f"((d)[2]),"+f"((d)[3]) \
                 : "r"((a).x),"r"((a).y),"r"((a).z),"r"((a).w), \
                   "r"((b)[0]),"r"((b)[1]))

// ---------------- fused prepass (unchanged from R14) -------------------------
__global__ void prepass_all(const float* __restrict__ x,
                            const float* __restrict__ w) {
    __shared__ float t[32][33];
    const int tx = threadIdx.x, ty = threadIdx.y;   // 32 x 8

    if (blockIdx.z < NB) {
        const int n  = blockIdx.z;
        const int p0 = blockIdx.x * 32;
        const int c0 = blockIdx.y * 32;

        const float* xb = x + ((size_t)n * CIN + c0) * NPIX + p0;
        #pragma unroll
        for (int yy = ty; yy < 32; yy += 8)
            t[yy][tx] = xb[(size_t)yy * NPIX + tx];
        __syncthreads();

        size_t ob = ((size_t)n * NPIX + p0) * CIN + c0;
        #pragma unroll
        for (int yy = ty; yy < 32; yy += 8)
            g_xt[ob + (size_t)yy * CIN + tx] = to_tf32(t[tx][yy]);
    } else {
        const int b = blockIdx.y * gridDim.x + blockIdx.x;   // 0..783
        const int tl = ty * 32 + tx;
        const int idx = b * 256 + tl;
        if (idx == 0) g_tile_ctr = 0u;
        if (idx < WA_FLOATS / 4) {
            const int L  = idx & 31;
            int r = idx >> 5;
            const int ks = r & 3;  r >>= 2;
            const int mi = r & 1;  r >>= 1;
            const int wm = r & 3;  r >>= 2;
            const int ch  = r % NCHUNK;
            const int k0g = r / NCHUNK;
            const int cg = ch / 9, tap = ch - (ch / 9) * 9;
            const int row0 = k0g * 128 + wm * 32 + mi * 16 + (L >> 2);
            const int kc   = cg * 32 + ks * 8 + (L & 3);
            float4 o;
            o.x = to_tf32(w[(size_t)(row0      * CIN + kc    ) * 9 + tap]);
            o.y = to_tf32(w[(size_t)((row0 + 8)* CIN + kc    ) * 9 + tap]);
            o.z = to_tf32(w[(size_t)(row0      * CIN + kc + 4) * 9 + tap]);
            o.w = to_tf32(w[(size_t)((row0 + 8)* CIN + kc + 4) * 9 + tap]);
            reinterpret_cast<float4*>(g_wa)[idx] = o;
        }
    }
}

// ---------------- main kernel: persistent, static 2-stage pipeline ----------
__global__ __launch_bounds__(256, 2)
void conv_mma_kernel(const float* __restrict__ bias, float* __restrict__ out)
{
    extern __shared__ __align__(16) char dsm_raw[];
    __shared__ unsigned s_tile;

    const int tid = threadIdx.x;
    const int wid = tid >> 5;
    const int L   = tid & 31;
    const int wm  = wid & 3;             // M quarter
    const int wn  = wid >> 2;            // output row within 2-row tile

    uint32_t raw = smem_u32(dsm_raw);
    uint32_t sm  = (raw + 127u) & ~127u;
    uint32_t bB[2] = { sm, sm + B_STAGE };

    // ---- per-lane B ldmatrix constants ----
    const int bLane  = ((L >> 4) & 1) * 8 + (L & 7);
    const int bkg    = (L >> 3) & 1;
    const int bsLane = 48 + (L & 7);
    const int bskg   = (L >> 3) & 1;

    const uint4* __restrict__ aP = reinterpret_cast<const uint4*>(g_wa);

    // ---- B halo staging (stateless) ----
    auto stageB = [&](int tn, int tr0, int cgc, int slice, uint32_t buf) {
        const int slot = slice * 256 + tid;
        if (slot < B_SLOTS) {
            const int ri = slot >> 3, v = slot & 7;
            const int inRow = ri / 58;
            const int inCol = ri - inRow * 58;
            const int r = tr0 - 1 + inRow;
            const int w = inCol - 1;
            const bool ok = ((unsigned)r < HH) & ((unsigned)w < WW);
            const int pix = ok ? (r * WW + w) : 0;
            const float* src = g_xt + ((size_t)tn * NPIX + pix) * CIN
                                    + (cgc << 5) + (v << 2);
            uint32_t bo = (uint32_t)(ri << 7) + (v << 4);
            bo ^= (bo >> 3) & 0x70;
            CP16(buf + bo, src, ok ? 16u : 0u);
        }
    };
    // B fragment loader for (base row Cw, ks)
    auto ldsmB = [&](uint32_t (&bt)[7][2], uint32_t sB, int Cw, int ks) {
        const int riP = Cw + bLane;
        #pragma unroll
        for (int pi = 0; pi < 3; ++pi) {
            const int ri = riP + pi * 16;
            const int c16 = (ks * 2 + bkg) ^ (ri & 7);
            LDSM4(&bt[pi * 2][0], sB + (uint32_t)(ri << 7) + (c16 << 4));
        }
        const int riS = Cw + bsLane;
        const int c16 = (ks * 2 + bskg) ^ (riS & 7);
        LDSM2(bt[6], sB + (uint32_t)(riS << 7) + (c16 << 4));
    };

    float acc[2][7][4];
    #pragma unroll
    for (int mi = 0; mi < 2; ++mi)
        #pragma unroll
        for (int ni = 0; ni < 7; ++ni)
            #pragma unroll
            for (int q = 0; q < 4; ++q)
                acc[mi][ni][q] = 0.0f;

    // ---- acquire first tile ----
    if (tid == 0) s_tile = atomicAdd(&g_tile_ctr, 1u);
    __syncthreads();
    if ((int)s_tile >= NTILES) return;
    int n, r0, k0g;
    {
        const int t = (int)s_tile;
        n = t / 56;
        const int rem = t - n * 56;
        k0g = rem & 1;
        r0 = (rem >> 1) << 1;
    }
    // prologue: full B halo for c-group 0
    #pragma unroll
    for (int t = 0; t < 8; ++t) stageB(n, r0, 0, t, bB[0]);
    CP_COMMIT();

    int nn = 0, nr0 = 0, nk0g = 0;
    bool vN = false;
    int lc = 0, tap = 0, cg = 0;

    // ---- persistent main loop: barrier only at c-group boundaries ----
    while (true) {
        if (tap == 0) {
            CP_WAIT0();
            __syncthreads();
            if (lc == 63) {
                const unsigned tt = s_tile;
                vN = (tt < NTILES);
                if (vN) {
                    nn = tt / 56;
                    const int rem = (int)tt - nn * 56;
                    nk0g = rem & 1;
                    nr0 = (rem >> 1) << 1;
                }
            }
        }
        if (lc == 61 && tid == 0) s_tile = atomicAdd(&g_tile_ctr, 1u);

        // stage one B halo slice for the next c-group / next tile
        if (tap < 8) {
            if (cg < 7)  { stageB(n,  r0,  cg + 1, tap, bB[(cg + 1) & 1]); CP_COMMIT(); }
            else if (vN) { stageB(nn, nr0, 0,      tap, bB[0]);            CP_COMMIT(); }
        }

        // ---- compute chunk lc: static 2-stage pipeline, branch-free ----
        {
            const uint32_t sB = bB[cg & 1];
            const int kh = tap / 3 - 1;
            const int kw = tap - (tap / 3) * 3 - 1;
            const int Cw = (wn + 1 + kh) * 58 + 1 + kw;

            const uint4* aC = aP + (size_t)(((k0g * NCHUNK + lc) * 4 + wm) * 2) * 128 + L;
            uint4 a0[2], a1[2];
            uint32_t bt0[7][2], bt1[7][2];

            // prologue: ks0 + ks1 fragments
            a0[0] = aC[0];   a0[1] = aC[128];
            a1[0] = aC[32];  a1[1] = aC[160];
            ldsmB(bt0, sB, Cw, 0);
            ldsmB(bt1, sB, Cw, 1);

            // ks0 MMAs, then fetch ks2 into slot 0
            #pragma unroll
            for (int ni = 0; ni < 7; ++ni) {
                MMAT(acc[0][ni], a0[0], bt0[ni]);
                MMAT(acc[1][ni], a0[1], bt0[ni]);
            }
            a0[0] = aC[64];  a0[1] = aC[192];
            ldsmB(bt0, sB, Cw, 2);

            // ks1 MMAs, then fetch ks3 into slot 1
            #pragma unroll
            for (int ni = 0; ni < 7; ++ni) {
                MMAT(acc[0][ni], a1[0], bt1[ni]);
                MMAT(acc[1][ni], a1[1], bt1[ni]);
            }
            a1[0] = aC[96];  a1[1] = aC[224];
            ldsmB(bt1, sB, Cw, 3);

            // ks2 MMAs
            #pragma unroll
            for (int ni = 0; ni < 7; ++ni) {
                MMAT(acc[0][ni], a0[0], bt0[ni]);
                MMAT(acc[1][ni], a0[1], bt0[ni]);
            }
            // ks3 MMAs
            #pragma unroll
            for (int ni = 0; ni < 7; ++ni) {
                MMAT(acc[0][ni], a1[0], bt1[ni]);
                MMAT(acc[1][ni], a1[1], bt1[ni]);
            }
        }

        if (lc == NCHUNK - 1) {
            // ---- epilogue ----
            const int gID = L >> 2;
            const int tig = L & 3;
            const int r   = r0 + wn;
            #pragma unroll
            for (int mi = 0; mi < 2; ++mi) {
                const int kbase = k0g * 128 + wm * 32 + mi * 16 + gID;
                const float b0 = bias[kbase];
                const float b1 = bias[kbase + 8];
                float* o0 = out + (((size_t)n * KOUT + kbase)     * HH + r) * WW;
                float* o1 = out + (((size_t)n * KOUT + kbase + 8) * HH + r) * WW;
                #pragma unroll
                for (int ni = 0; ni < 7; ++ni) {
                    const int c = ni * 8 + tig * 2;
                    float2 v0 = make_float2(acc[mi][ni][0] + b0, acc[mi][ni][1] + b0);
                    float2 v1 = make_float2(acc[mi][ni][2] + b1, acc[mi][ni][3] + b1);
                    *reinterpret_cast<float2*>(o0 + c) = v0;
                    *reinterpret_cast<float2*>(o1 + c) = v1;
                }
            }
            if (!vN) break;
            #pragma unroll
            for (int mi = 0; mi < 2; ++mi)
                #pragma unroll
                for (int ni = 0; ni < 7; ++ni)
                    #pragma unroll
                    for (int q = 0; q < 4; ++q)
                        acc[mi][ni][q] = 0.0f;
            n = nn; r0 = nr0; k0g = nk0g;
            vN = false;
            lc = 0; tap = 0; cg = 0;
        } else {
            ++lc;
            if (++tap == 9) { tap = 0; ++cg; }
        }
    }
}

// ---------------- launch -----------------------------------------------------
extern "C" void kernel_launch(void* const* d_in, const int* in_sizes, int n_in,
                              void* d_out, int out_size)
{
    const float* x    = (const float*)d_in[0];
    const float* wgt  = (const float*)d_in[1];
    const float* bias = (const float*)d_in[2];
    float* out        = (float*)d_out;

    cudaFuncSetAttribute(conv_mma_kernel,
                         cudaFuncAttributeMaxDynamicSharedMemorySize, SM_DYN);

    {
        dim3 g(NPIX / 32, CIN / 32, NB + 1);   // z=NB: g_wa fill + ctr reset
        dim3 b(32, 8);
        prepass_all<<<g, b>>>(x, wgt);
    }

    conv_mma_kernel<<<296, 256, SM_DYN>>>(bias, out);   // persistent: 2 CTAs/SM
}